// round 12
// baseline (speedup 1.0000x reference)
#include <cuda_runtime.h>
#include <cuda_fp16.h>
#include <math.h>
#include <stdint.h>

#define DM 768
#define DFF 3072
#define NH 12
#define DK 64
#define BATCH 2
#define SEQ 2048
#define MROWS (BATCH*SEQ)            // 4096
#define BHN (BATCH*NH)               // 24
#define OUT_ELEMS (MROWS*DM)
#define ATT_ELEMS ((size_t)BHN*SEQ*SEQ)

// ---- scratch (allocation-free: __device__ globals) ----
__device__ __align__(16) __half g_xh [MROWS*DM];
__device__ __align__(16) __half g_Wqh[DM*DM];
__device__ __align__(16) __half g_Wkh[DM*DM];
__device__ __align__(16) __half g_Wvh[DM*DM];
__device__ __align__(16) __half g_Woh[DM*DM];
__device__ __align__(16) __half g_W1h[DM*DFF];
__device__ __align__(16) __half g_W2h[DFF*DM];
__device__ __align__(16) __half g_Qh [MROWS*DM];
__device__ __align__(16) __half g_Kh [MROWS*DM];
__device__ __align__(16) __half g_Vh [MROWS*DM];
__device__ __align__(16) __half g_ctxh[MROWS*DM];
__device__ __align__(16) __half g_aoh[MROWS*DM];
__device__ __align__(16) __half g_hh [MROWS*DFF];
__device__ __align__(16) float g_P[BHN*(size_t)SEQ*SEQ];
__device__ __align__(16) float g_t0[MROWS*DM];
__device__ __align__(16) float g_ao[MROWS*DM];
__device__ __align__(16) float g_f [MROWS*DM];

__device__ __forceinline__ uint32_t smem_u32(const void* p) {
    uint32_t a;
    asm("{ .reg .u64 t; cvta.to.shared.u64 t, %1; cvt.u32.u64 %0, t; }"
        : "=r"(a) : "l"(p));
    return a;
}

__device__ __forceinline__ void mma16816(float* c, const uint32_t* a, const uint32_t* b) {
    asm volatile(
        "mma.sync.aligned.m16n8k16.row.col.f32.f16.f16.f32 "
        "{%0,%1,%2,%3}, {%4,%5,%6,%7}, {%8,%9}, {%0,%1,%2,%3};"
        : "+f"(c[0]), "+f"(c[1]), "+f"(c[2]), "+f"(c[3])
        : "r"(a[0]), "r"(a[1]), "r"(a[2]), "r"(a[3]), "r"(b[0]), "r"(b[1]));
}

#define LDSM_X4(r0,r1,r2,r3,addr) \
    asm volatile("ldmatrix.sync.aligned.m8n8.x4.shared.b16 {%0,%1,%2,%3}, [%4];" \
        : "=r"(r0),"=r"(r1),"=r"(r2),"=r"(r3) : "r"(addr))
#define LDSM_X4T(r0,r1,r2,r3,addr) \
    asm volatile("ldmatrix.sync.aligned.m8n8.x4.trans.shared.b16 {%0,%1,%2,%3}, [%4];" \
        : "=r"(r0),"=r"(r1),"=r"(r2),"=r"(r3) : "r"(addr))
#define CP_ASYNC16(saddr, gptr) \
    asm volatile("cp.async.cg.shared.global [%0], [%1], 16;" :: "r"(saddr), "l"(gptr))
#define CP_COMMIT() asm volatile("cp.async.commit_group;")
#define CP_WAIT_GROUP(n) asm volatile("cp.async.wait_group %0;" :: "n"(n))

// ============================================================
// f32 -> f16 convert
// ============================================================
__global__ __launch_bounds__(256) void f2h_kernel(
    const float* __restrict__ X, __half* __restrict__ Y)
{
    int i = (blockIdx.x * 256 + threadIdx.x) * 4;
    float4 v = *(const float4*)(X + i);
    *(__half2*)(Y + i)     = __floats2half2_rn(v.x, v.y);
    *(__half2*)(Y + i + 2) = __floats2half2_rn(v.z, v.w);
}

// ============================================================
// fp16 GEMM (unchanged from R10): 128x128x32, 3-stage cp.async.
// ============================================================
template<int RELU, int OUTF32, int OUTHALF>
__global__ __launch_bounds__(256, 2) void hgemm(
    const __half* __restrict__ A, const __half* __restrict__ W,
    const float* __restrict__ bias, const float* __restrict__ resid,
    float* __restrict__ C, __half* __restrict__ Ch,
    int M, int N, int K)
{
    extern __shared__ char dsm[];
    uint32_t sb = smem_u32(dsm);

    int tid = threadIdx.x, lane = tid & 31, warp = tid >> 5;
    int wm = warp >> 1, wn = warp & 1;
    int g = lane >> 2, tg = lane & 3;
    int bm = blockIdx.y * 128, bn = blockIdx.x * 128;

    float acc[2][8][4];
#pragma unroll
    for (int mt = 0; mt < 2; mt++)
#pragma unroll
        for (int nt = 0; nt < 8; nt++)
#pragma unroll
            for (int q = 0; q < 4; q++) acc[mt][nt][q] = 0.f;

    const int NC = K / 32;
    int ar0 = tid >> 2, ac0 = tid & 3;
    int bk0 = tid >> 4, bc0 = tid & 15;

#define LOAD_STAGE(stg, k0) { \
    uint32_t base = sb + (stg) * 16384; \
    _Pragma("unroll") \
    for (int j = 0; j < 2; j++) { \
        int r = ar0 + j * 64, c = ac0; \
        uint32_t sa = base + r * 64 + ((c ^ ((r >> 1) & 3)) << 4); \
        CP_ASYNC16(sa, A + (size_t)(bm + r) * K + (k0) + c * 8); \
    } \
    _Pragma("unroll") \
    for (int j = 0; j < 2; j++) { \
        int k = bk0 + j * 16, c = bc0; \
        uint32_t sa = base + 8192 + k * 256 + ((c ^ (k & 7)) << 4); \
        CP_ASYNC16(sa, W + (size_t)((k0) + k) * N + bn + c * 8); \
    } \
    CP_COMMIT(); }

    LOAD_STAGE(0, 0);
    LOAD_STAGE(1, 32);

    int st = 0;
    for (int i = 0; i < NC; i++) {
        CP_WAIT_GROUP(1);
        __syncthreads();
        if (i + 2 < NC) {
            int st2 = st + 2; if (st2 >= 3) st2 -= 3;
            LOAD_STAGE(st2, (i + 2) * 32);
        } else {
            CP_COMMIT();
        }
        uint32_t base = sb + st * 16384;
#pragma unroll
        for (int kk = 0; kk < 2; kk++) {
            int ks16 = kk * 16;
            uint32_t a[2][4];
#pragma unroll
            for (int mt = 0; mt < 2; mt++) {
                int row = wm * 32 + mt * 16 + (lane & 15);
                int ch = (ks16 >> 3) + (lane >> 4);
                uint32_t ad = base + row * 64 + ((ch ^ ((row >> 1) & 3)) << 4);
                LDSM_X4(a[mt][0], a[mt][1], a[mt][2], a[mt][3], ad);
            }
#pragma unroll
            for (int p = 0; p < 4; p++) {
                int k = ks16 + (lane & 15);
                int ch = wn * 8 + p * 2 + (lane >> 4);
                uint32_t bd = base + 8192 + k * 256 + ((ch ^ (k & 7)) << 4);
                uint32_t b0, b1, b2, b3;
                LDSM_X4T(b0, b1, b2, b3, bd);
                uint32_t f0[2] = {b0, b1}, f1[2] = {b2, b3};
#pragma unroll
                for (int mt = 0; mt < 2; mt++) {
                    mma16816(acc[mt][2*p],     a[mt], f0);
                    mma16816(acc[mt][2*p + 1], a[mt], f1);
                }
            }
        }
        st++; if (st >= 3) st = 0;
    }
#undef LOAD_STAGE

#pragma unroll
    for (int mt = 0; mt < 2; mt++) {
#pragma unroll
        for (int nt = 0; nt < 8; nt++) {
            int c = bn + wn * 64 + nt * 8 + tg * 2;
            float bx = bias[c], by = bias[c + 1];
#pragma unroll
            for (int hh = 0; hh < 2; hh++) {
                int r = bm + wm * 32 + mt * 16 + g + hh * 8;
                float v0 = acc[mt][nt][hh*2+0] + bx;
                float v1 = acc[mt][nt][hh*2+1] + by;
                if (OUTF32 && resid) {
                    float2 rv = *(const float2*)(resid + (size_t)r * N + c);
                    v0 += rv.x; v1 += rv.y;
                }
                if (RELU) { v0 = fmaxf(v0, 0.f); v1 = fmaxf(v1, 0.f); }
                if (OUTF32)
                    *(float2*)(C + (size_t)r * N + c) = make_float2(v0, v1);
                if (OUTHALF)
                    *(__half2*)(Ch + (size_t)r * N + c) = __floats2half2_rn(v0, v1);
            }
        }
    }
}

// ============================================================
// Fused attention: scores + softmax + attn-write + PV, one block per
// (bh, 128-q-tile). Two passes over 16 K-tiles (pass1 stats, pass2 emit).
// Dyn smem: Qs 16K | Ks 2x16K | Vs 2x16K | stage f32 128x132 66K |
//           Ph fp16 128x128 32K | mrun/srun 1K   = 183296 B
// ============================================================
#define AQS 0
#define AKS 16384
#define AVS 49152
#define AST 81920
#define APH 149504
#define AMR 182272
#define ASR 182784
#define ATTN_SMEM 183296

__global__ __launch_bounds__(256, 1) void attn_fused(
    const __half* __restrict__ Qh, const __half* __restrict__ Kh,
    const __half* __restrict__ Vh, const unsigned char* __restrict__ mask,
    float* __restrict__ P, __half* __restrict__ ctxh)
{
    extern __shared__ char dsm[];
    uint32_t sb = smem_u32(dsm);
    float* stage  = (float*)(dsm + AST);
    float* mrun_s = (float*)(dsm + AMR);
    float* srun_s = (float*)(dsm + ASR);

    int tid = threadIdx.x, lane = tid & 31, warp = tid >> 5;
    int wm = warp >> 1, wn = warp & 1;
    int g = lane >> 2, tg = lane & 3;

    int bh = blockIdx.y, b = bh / NH, h = bh % NH;
    int bq = blockIdx.x * 128;
    const __half* Qb = Qh + (size_t)(b * SEQ) * DM + h * DK;
    const __half* Kb = Kh + (size_t)(b * SEQ) * DM + h * DK;
    const __half* Vb = Vh + (size_t)(b * SEQ) * DM + h * DK;
    const unsigned char* mb = mask + (size_t)b * SEQ * SEQ;
    float* Pb = P + (size_t)bh * SEQ * SEQ;

    // tile loaders: 128 rows x 64 halves (8 chunks of 16B), swizzle ch^(r&7)
    int lr = tid >> 1, lc0 = (tid & 1) * 4;

#define LOAD_TILE(OFF, SRC, row0) { \
    _Pragma("unroll") \
    for (int j = 0; j < 4; j++) { \
        int ch = lc0 + j; \
        uint32_t sa = sb + (OFF) + lr * 128 + ((ch ^ (lr & 7)) << 4); \
        CP_ASYNC16(sa, (SRC) + (size_t)((row0) + lr) * DM + ch * 8); \
    } }

    if (tid < 128) { mrun_s[tid] = -1e30f; srun_s[tid] = 0.f; }

    // ---- preload Q + K0 (group), K1 (group) ----
    LOAD_TILE(AQS, Qb, bq);
    LOAD_TILE(AKS, Kb, 0);
    CP_COMMIT();
    LOAD_TILE(AKS + 16384, Kb, 128);
    CP_COMMIT();
    CP_WAIT_GROUP(1);
    __syncthreads();

    // ---- Q fragments (persist across both passes) ----
    uint32_t aq[2][4][4];
#pragma unroll
    for (int mt = 0; mt < 2; mt++)
#pragma unroll
        for (int kg = 0; kg < 4; kg++) {
            int row = wm * 32 + mt * 16 + (lane & 15);
            int ch = (kg << 1) + (lane >> 4);
            uint32_t ad = sb + AQS + row * 128 + ((ch ^ (row & 7)) << 4);
            LDSM_X4(aq[mt][kg][0], aq[mt][kg][1], aq[mt][kg][2], aq[mt][kg][3], ad);
        }

#define SCORES_MMA(buf, sacc) { \
    uint32_t kbase = sb + AKS + (buf) * 16384; \
    _Pragma("unroll") \
    for (int kg = 0; kg < 4; kg++) { \
        _Pragma("unroll") \
        for (int np = 0; np < 4; np++) { \
            int n0 = wn * 64 + np * 16; \
            int row = n0 + (lane & 7) + ((lane >> 4) << 3); \
            int ch = (kg << 1) + ((lane >> 3) & 1); \
            uint32_t ad = kbase + row * 128 + ((ch ^ (row & 7)) << 4); \
            uint32_t b0, b1, b2, b3; \
            LDSM_X4(b0, b1, b2, b3, ad); \
            uint32_t f0[2] = {b0, b1}, f1[2] = {b2, b3}; \
            _Pragma("unroll") \
            for (int mt = 0; mt < 2; mt++) { \
                mma16816(sacc[mt][np*2],   aq[mt][kg], f0); \
                mma16816(sacc[mt][np*2+1], aq[mt][kg], f1); \
            } \
        } \
    } }

#define STAGE_FRAGS(sacc) { \
    _Pragma("unroll") \
    for (int mt = 0; mt < 2; mt++) \
        _Pragma("unroll") \
        for (int nt = 0; nt < 8; nt++) \
            _Pragma("unroll") \
            for (int hh = 0; hh < 2; hh++) { \
                int r = wm * 32 + mt * 16 + hh * 8 + g; \
                int c = wn * 64 + nt * 8 + tg * 2; \
                *(float2*)(stage + r * 132 + c) = make_float2( \
                    sacc[mt][nt][hh*2] * 0.125f, sacc[mt][nt][hh*2+1] * 0.125f); \
            } }

    // ================= PASS 1: stats =================
    for (int kt = 0; kt < 16; kt++) {
        int buf = kt & 1;
        float sacc[2][8][4];
#pragma unroll
        for (int mt = 0; mt < 2; mt++)
#pragma unroll
            for (int nt = 0; nt < 8; nt++)
#pragma unroll
                for (int q = 0; q < 4; q++) sacc[mt][nt][q] = 0.f;

        SCORES_MMA(buf, sacc);
        STAGE_FRAGS(sacc);
        __syncthreads();
        if (kt + 2 < 16) LOAD_TILE(AKS + buf * 16384, Kb, (kt + 2) * 128);
        CP_COMMIT();

        // warp-per-row online softmax stats
#pragma unroll 4
        for (int it = 0; it < 16; it++) {
            int r = warp + it * 8;
            float4 v = *(float4*)(stage + r * 132 + lane * 4);
            uint32_t mw = *(const uint32_t*)(mb + (size_t)(bq + r) * SEQ + kt * 128 + lane * 4);
            if (mw & 0x000000FFu) v.x = -1e9f;
            if (mw & 0x0000FF00u) v.y = -1e9f;
            if (mw & 0x00FF0000u) v.z = -1e9f;
            if (mw & 0xFF000000u) v.w = -1e9f;
            float lm = fmaxf(fmaxf(v.x, v.y), fmaxf(v.z, v.w));
#pragma unroll
            for (int o = 16; o > 0; o >>= 1)
                lm = fmaxf(lm, __shfl_xor_sync(0xffffffffu, lm, o));
            float mold = mrun_s[r];
            float mnew = fmaxf(mold, lm);
            float ps = __expf(v.x - mnew) + __expf(v.y - mnew)
                     + __expf(v.z - mnew) + __expf(v.w - mnew);
#pragma unroll
            for (int o = 16; o > 0; o >>= 1)
                ps += __shfl_xor_sync(0xffffffffu, ps, o);
            if (lane == 0) {
                srun_s[r] = srun_s[r] * __expf(mold - mnew) + ps;
                mrun_s[r] = mnew;
            }
        }
        CP_WAIT_GROUP(1);
        __syncthreads();
    }

    if (tid < 128) srun_s[tid] = 1.f / srun_s[tid];
    __syncthreads();

    // ================= PASS 2: emit attn + PV =================
    float ctx[2][4][4];
#pragma unroll
    for (int mt = 0; mt < 2; mt++)
#pragma unroll
        for (int nt = 0; nt < 4; nt++)
#pragma unroll
            for (int q = 0; q < 4; q++) ctx[mt][nt][q] = 0.f;

    LOAD_TILE(AKS, Kb, 0);
    LOAD_TILE(AVS, Vb, 0);
    CP_COMMIT();
    LOAD_TILE(AKS + 16384, Kb, 128);
    LOAD_TILE(AVS + 16384, Vb, 128);
    CP_COMMIT();
    CP_WAIT_GROUP(1);
    __syncthreads();

    for (int kt = 0; kt < 16; kt++) {
        int buf = kt & 1;
        float sacc[2][8][4];
#pragma unroll
        for (int mt = 0; mt < 2; mt++)
#pragma unroll
            for (int nt = 0; nt < 8; nt++)
#pragma unroll
                for (int q = 0; q < 4; q++) sacc[mt][nt][q] = 0.f;

        SCORES_MMA(buf, sacc);
        STAGE_FRAGS(sacc);
        __syncthreads();
        if (kt + 2 < 16) LOAD_TILE(AKS + buf * 16384, Kb, (kt + 2) * 128);
        CP_COMMIT();

        // normalize, write attn (coalesced), drop fp16 into Ph
#pragma unroll 4
        for (int it = 0; it < 16; it++) {
            int r = warp + it * 8;
            float4 v = *(float4*)(stage + r * 132 + lane * 4);
            uint32_t mw = *(const uint32_t*)(mb + (size_t)(bq + r) * SEQ + kt * 128 + lane * 4);
            if (mw & 0x000000FFu) v.x = -1e9f;
            if (mw & 0x0000FF00u) v.y = -1e9f;
            if (mw & 0x00FF0000u) v.z = -1e9f;
            if (mw & 0xFF000000u) v.w = -1e9f;
            float m = mrun_s[r], iv = srun_s[r];
            float4 p;
            p.x = __expf(v.x - m) * iv;
            p.y = __expf(v.y - m) * iv;
            p.z = __expf(v.z - m) * iv;
            p.w = __expf(v.w - m) * iv;
            *(float4*)(Pb + (size_t)(bq + r) * SEQ + kt * 128 + lane * 4) = p;
            __half2 h0 = __floats2half2_rn(p.x, p.y);
            __half2 h1 = __floats2half2_rn(p.z, p.w);
            *(uint2*)(dsm + APH + r * 256 + (((lane >> 1) ^ (r & 7)) << 4)
                      + ((lane & 1) << 3)) = make_uint2(*(uint32_t*)&h0, *(uint32_t*)&h1);
        }
        __syncthreads();

        // PV mma: ctx += Ph(128x128) @ V(128x64); warp owns 32 rows x 32 d
        {
            uint32_t vbase = sb + AVS + buf * 16384;
#pragma unroll
            for (int kg8 = 0; kg8 < 8; kg8++) {
                uint32_t pa[2][4];
#pragma unroll
                for (int mt = 0; mt < 2; mt++) {
                    int row = wm * 32 + mt * 16 + (lane & 15);
                    int ch = (kg8 << 1) + (lane >> 4);
                    uint32_t ad = sb + APH + row * 256 + ((ch ^ (row & 7)) << 4);
                    LDSM_X4(pa[mt][0], pa[mt][1], pa[mt][2], pa[mt][3], ad);
                }
#pragma unroll
                for (int vv = 0; vv < 2; vv++) {
                    int k = kg8 * 16 + (lane & 15);
                    int ch = wn * 4 + vv * 2 + (lane >> 4);
                    uint32_t ad = vbase + k * 128 + ((ch ^ (k & 7)) << 4);
                    uint32_t b0, b1, b2, b3;
                    LDSM_X4T(b0, b1, b2, b3, ad);
                    uint32_t f0[2] = {b0, b1}, f1[2] = {b2, b3};
#pragma unroll
                    for (int mt = 0; mt < 2; mt++) {
                        mma16816(ctx[mt][vv*2],   pa[mt], f0);
                        mma16816(ctx[mt][vv*2+1], pa[mt], f1);
                    }
                }
            }
        }
        __syncthreads();
        if (kt + 2 < 16) LOAD_TILE(AVS + buf * 16384, Vb, (kt + 2) * 128);
        CP_COMMIT();
        CP_WAIT_GROUP(2);
        __syncthreads();
    }

    // ctx out (fp16, feeds Wo GEMM)
#pragma unroll
    for (int mt = 0; mt < 2; mt++)
#pragma unroll
        for (int nt = 0; nt < 4; nt++) {
            int dn = wn * 32 + nt * 8 + tg * 2;
#pragma unroll
            for (int hh = 0; hh < 2; hh++) {
                int r = bq + wm * 32 + mt * 16 + hh * 8 + g;
                *(__half2*)(ctxh + (size_t)(b * SEQ + r) * DM + h * DK + dn) =
                    __floats2half2_rn(ctx[mt][nt][hh*2], ctx[mt][nt][hh*2+1]);
            }
        }
#undef LOAD_TILE
#undef SCORES_MMA
#undef STAGE_FRAGS
}

// ============================================================
// LayerNorm over last dim (768); optional fp16 copy of output.
// ============================================================
template<int OUTH>
__global__ __launch_bounds__(256) void layernorm_kernel(
    const float* __restrict__ X, const float* __restrict__ gam,
    const float* __restrict__ bet, float* __restrict__ Y, __half* __restrict__ Yh)
{
    int row = blockIdx.x;
    const float* x = X + (size_t)row * DM;
    float* y = Y + (size_t)row * DM;
    int tid = threadIdx.x;
    int lane = tid & 31, warp = tid >> 5;
    __shared__ float sw[8];

    float v0 = x[tid], v1 = x[tid + 256], v2 = x[tid + 512];
    float s = v0 + v1 + v2;
#pragma unroll
    for (int o = 16; o > 0; o >>= 1) s += __shfl_xor_sync(0xffffffffu, s, o);
    if (lane == 0) sw[warp] = s;
    __syncthreads();
    s = 0.f;
#pragma unroll
    for (int w = 0; w < 8; w++) s += sw[w];
    float mean = s * (1.f / 768.f);
    __syncthreads();

    float d0 = v0 - mean, d1 = v1 - mean, d2 = v2 - mean;
    float sq = d0 * d0 + d1 * d1 + d2 * d2;
#pragma unroll
    for (int o = 16; o > 0; o >>= 1) sq += __shfl_xor_sync(0xffffffffu, sq, o);
    if (lane == 0) sw[warp] = sq;
    __syncthreads();
    sq = 0.f;
#pragma unroll
    for (int w = 0; w < 8; w++) sq += sw[w];
    float var = sq * (1.f / 768.f);
    float rstd = rsqrtf(var + 1e-5f);

    float o0 = d0 * rstd * gam[tid]       + bet[tid];
    float o1 = d1 * rstd * gam[tid + 256] + bet[tid + 256];
    float o2 = d2 * rstd * gam[tid + 512] + bet[tid + 512];
    y[tid] = o0; y[tid + 256] = o1; y[tid + 512] = o2;
    if (OUTH) {
        __half* yh = Yh + (size_t)row * DM;
        yh[tid] = __float2half(o0);
        yh[tid + 256] = __float2half(o1);
        yh[tid + 512] = __float2half(o2);
    }
}

// ============================================================
#define HG_SMEM 49152

extern "C" void kernel_launch(void* const* d_in, const int* in_sizes, int n_in,
                              void* d_out, int out_size)
{
    const float* x    = (const float*)d_in[0];
    const unsigned char* mask = (const unsigned char*)d_in[1];
    const float* Wq = (const float*)d_in[2];
    const float* bq = (const float*)d_in[3];
    const float* Wk = (const float*)d_in[4];
    const float* bk = (const float*)d_in[5];
    const float* Wv = (const float*)d_in[6];
    const float* bv = (const float*)d_in[7];
    const float* Wo = (const float*)d_in[8];
    const float* bo = (const float*)d_in[9];
    const float* ln1g = (const float*)d_in[10];
    const float* ln1b = (const float*)d_in[11];
    const float* W1 = (const float*)d_in[12];
    const float* b1 = (const float*)d_in[13];
    const float* W2 = (const float*)d_in[14];
    const float* b2 = (const float*)d_in[15];
    const float* ln2g = (const float*)d_in[16];
    const float* ln2b = (const float*)d_in[17];
    float* out = (float*)d_out;

    __half *xh, *Wqh, *Wkh, *Wvh, *Woh, *W1h, *W2h;
    __half *Qh, *Kh, *Vh, *ctxh, *aoh, *hh;
    float *Pd, *t0, *ao, *f;
    cudaGetSymbolAddress((void**)&xh,   g_xh);
    cudaGetSymbolAddress((void**)&Wqh,  g_Wqh);
    cudaGetSymbolAddress((void**)&Wkh,  g_Wkh);
    cudaGetSymbolAddress((void**)&Wvh,  g_Wvh);
    cudaGetSymbolAddress((void**)&Woh,  g_Woh);
    cudaGetSymbolAddress((void**)&W1h,  g_W1h);
    cudaGetSymbolAddress((void**)&W2h,  g_W2h);
    cudaGetSymbolAddress((void**)&Qh,   g_Qh);
    cudaGetSymbolAddress((void**)&Kh,   g_Kh);
    cudaGetSymbolAddress((void**)&Vh,   g_Vh);
    cudaGetSymbolAddress((void**)&ctxh, g_ctxh);
    cudaGetSymbolAddress((void**)&aoh,  g_aoh);
    cudaGetSymbolAddress((void**)&hh,   g_hh);
    cudaGetSymbolAddress((void**)&Pd,   g_P);
    cudaGetSymbolAddress((void**)&t0,   g_t0);
    cudaGetSymbolAddress((void**)&ao,   g_ao);
    cudaGetSymbolAddress((void**)&f,    g_f);

    cudaFuncSetAttribute(hgemm<0,0,1>, cudaFuncAttributeMaxDynamicSharedMemorySize, HG_SMEM);
    cudaFuncSetAttribute(hgemm<0,1,0>, cudaFuncAttributeMaxDynamicSharedMemorySize, HG_SMEM);
    cudaFuncSetAttribute(hgemm<1,0,1>, cudaFuncAttributeMaxDynamicSharedMemorySize, HG_SMEM);
    cudaFuncSetAttribute(attn_fused, cudaFuncAttributeMaxDynamicSharedMemorySize, ATTN_SMEM);

    float* Pbuf = ((size_t)out_size >= (size_t)OUT_ELEMS + ATT_ELEMS)
                ? (out + OUT_ELEMS) : Pd;

    f2h_kernel<<<(MROWS*DM)/1024, 256>>>(x,  xh);
    f2h_kernel<<<(DM*DM)/1024,  256>>>(Wq, Wqh);
    f2h_kernel<<<(DM*DM)/1024,  256>>>(Wk, Wkh);
    f2h_kernel<<<(DM*DM)/1024,  256>>>(Wv, Wvh);
    f2h_kernel<<<(DM*DM)/1024,  256>>>(Wo, Woh);
    f2h_kernel<<<(DM*DFF)/1024, 256>>>(W1, W1h);
    f2h_kernel<<<(DFF*DM)/1024, 256>>>(W2, W2h);

    dim3 g768(DM / 128, MROWS / 128);
    hgemm<0,0,1><<<g768, 256, HG_SMEM>>>(xh, Wqh, bq, nullptr, nullptr, Qh, MROWS, DM, DM);
    hgemm<0,0,1><<<g768, 256, HG_SMEM>>>(xh, Wkh, bk, nullptr, nullptr, Kh, MROWS, DM, DM);
    hgemm<0,0,1><<<g768, 256, HG_SMEM>>>(xh, Wvh, bv, nullptr, nullptr, Vh, MROWS, DM, DM);

    attn_fused<<<dim3(SEQ / 128, BHN), 256, ATTN_SMEM>>>(Qh, Kh, Vh, mask, Pbuf, ctxh);

    hgemm<0,1,0><<<g768, 256, HG_SMEM>>>(ctxh, Woh, bo, x, t0, nullptr, MROWS, DM, DM);
    layernorm_kernel<1><<<MROWS, 256>>>(t0, ln1g, ln1b, ao, aoh);

    dim3 gff1(DFF / 128, MROWS / 128);
    hgemm<1,0,1><<<gff1, 256, HG_SMEM>>>(aoh, W1h, b1, nullptr, nullptr, hh, MROWS, DFF, DM);
    hgemm<0,1,0><<<g768, 256, HG_SMEM>>>(hh, W2h, b2, ao, f, nullptr, MROWS, DM, DFF);
    layernorm_kernel<0><<<MROWS, 256>>>(f, ln2g, ln2b, out, nullptr);
}

// round 14
// speedup vs baseline: 1.3113x; 1.3113x over previous
#include <cuda_runtime.h>
#include <cuda_fp16.h>
#include <math.h>
#include <stdint.h>

#define DM 768
#define DFF 3072
#define NH 12
#define DK 64
#define BATCH 2
#define SEQ 2048
#define MROWS (BATCH*SEQ)            // 4096
#define BHN (BATCH*NH)               // 24
#define OUT_ELEMS (MROWS*DM)
#define ATT_ELEMS ((size_t)BHN*SEQ*SEQ)

// ---- scratch (allocation-free: __device__ globals) ----
__device__ __align__(16) __half g_xh [MROWS*DM];
__device__ __align__(16) __half g_Wqh[DM*DM];
__device__ __align__(16) __half g_Wkh[DM*DM];
__device__ __align__(16) __half g_Wvh[DM*DM];
__device__ __align__(16) __half g_Woh[DM*DM];
__device__ __align__(16) __half g_W1h[DM*DFF];
__device__ __align__(16) __half g_W2h[DFF*DM];
__device__ __align__(16) __half g_Qh [MROWS*DM];
__device__ __align__(16) __half g_Kh [MROWS*DM];
__device__ __align__(16) __half g_Vh [MROWS*DM];
__device__ __align__(16) __half g_Ph [BHN*(size_t)SEQ*SEQ];  // fp16 normalized P
__device__ __align__(16) __half g_ctxh[MROWS*DM];
__device__ __align__(16) __half g_aoh[MROWS*DM];
__device__ __align__(16) __half g_hh [MROWS*DFF];
__device__ __align__(16) float g_P[BHN*(size_t)SEQ*SEQ];
__device__ __align__(16) float g_t0[MROWS*DM];
__device__ __align__(16) float g_ao[MROWS*DM];
__device__ __align__(16) float g_f [MROWS*DM];

__device__ __forceinline__ uint32_t smem_u32(const void* p) {
    uint32_t a;
    asm("{ .reg .u64 t; cvta.to.shared.u64 t, %1; cvt.u32.u64 %0, t; }"
        : "=r"(a) : "l"(p));
    return a;
}

__device__ __forceinline__ void mma16816(float* c, const uint32_t* a, const uint32_t* b) {
    asm volatile(
        "mma.sync.aligned.m16n8k16.row.col.f32.f16.f16.f32 "
        "{%0,%1,%2,%3}, {%4,%5,%6,%7}, {%8,%9}, {%0,%1,%2,%3};"
        : "+f"(c[0]), "+f"(c[1]), "+f"(c[2]), "+f"(c[3])
        : "r"(a[0]), "r"(a[1]), "r"(a[2]), "r"(a[3]), "r"(b[0]), "r"(b[1]));
}

#define LDSM_X4(r0,r1,r2,r3,addr) \
    asm volatile("ldmatrix.sync.aligned.m8n8.x4.shared.b16 {%0,%1,%2,%3}, [%4];" \
        : "=r"(r0),"=r"(r1),"=r"(r2),"=r"(r3) : "r"(addr))
#define LDSM_X4T(r0,r1,r2,r3,addr) \
    asm volatile("ldmatrix.sync.aligned.m8n8.x4.trans.shared.b16 {%0,%1,%2,%3}, [%4];" \
        : "=r"(r0),"=r"(r1),"=r"(r2),"=r"(r3) : "r"(addr))
#define CP_ASYNC16(saddr, gptr) \
    asm volatile("cp.async.cg.shared.global [%0], [%1], 16;" :: "r"(saddr), "l"(gptr))
#define CP_COMMIT() asm volatile("cp.async.commit_group;")
#define CP_WAIT_GROUP(n) asm volatile("cp.async.wait_group %0;" :: "n"(n))

// ============================================================
// f32 -> f16 convert
// ============================================================
__global__ __launch_bounds__(256) void f2h_kernel(
    const float* __restrict__ X, __half* __restrict__ Y)
{
    int i = (blockIdx.x * 256 + threadIdx.x) * 4;
    float4 v = *(const float4*)(X + i);
    *(__half2*)(Y + i)     = __floats2half2_rn(v.x, v.y);
    *(__half2*)(Y + i + 2) = __floats2half2_rn(v.z, v.w);
}

// ============================================================
// fp16 GEMM: 128x128x32, 3-stage cp.async, ldmatrix frags, 8 warps.
// ============================================================
template<int RELU, int OUTF32, int OUTHALF>
__global__ __launch_bounds__(256, 2) void hgemm(
    const __half* __restrict__ A, const __half* __restrict__ W,
    const float* __restrict__ bias, const float* __restrict__ resid,
    float* __restrict__ C, __half* __restrict__ Ch,
    int M, int N, int K)
{
    extern __shared__ char dsm[];
    uint32_t sb = smem_u32(dsm);

    int tid = threadIdx.x, lane = tid & 31, warp = tid >> 5;
    int wm = warp >> 1, wn = warp & 1;
    int g = lane >> 2, tg = lane & 3;
    int bm = blockIdx.y * 128, bn = blockIdx.x * 128;

    float acc[2][8][4];
#pragma unroll
    for (int mt = 0; mt < 2; mt++)
#pragma unroll
        for (int nt = 0; nt < 8; nt++)
#pragma unroll
            for (int q = 0; q < 4; q++) acc[mt][nt][q] = 0.f;

    const int NC = K / 32;
    int ar0 = tid >> 2, ac0 = tid & 3;
    int bk0 = tid >> 4, bc0 = tid & 15;

#define LOAD_STAGE(stg, k0) { \
    uint32_t base = sb + (stg) * 16384; \
    _Pragma("unroll") \
    for (int j = 0; j < 2; j++) { \
        int r = ar0 + j * 64, c = ac0; \
        uint32_t sa = base + r * 64 + ((c ^ ((r >> 1) & 3)) << 4); \
        CP_ASYNC16(sa, A + (size_t)(bm + r) * K + (k0) + c * 8); \
    } \
    _Pragma("unroll") \
    for (int j = 0; j < 2; j++) { \
        int k = bk0 + j * 16, c = bc0; \
        uint32_t sa = base + 8192 + k * 256 + ((c ^ (k & 7)) << 4); \
        CP_ASYNC16(sa, W + (size_t)((k0) + k) * N + bn + c * 8); \
    } \
    CP_COMMIT(); }

    LOAD_STAGE(0, 0);
    LOAD_STAGE(1, 32);

    int st = 0;
    for (int i = 0; i < NC; i++) {
        CP_WAIT_GROUP(1);
        __syncthreads();
        if (i + 2 < NC) {
            int st2 = st + 2; if (st2 >= 3) st2 -= 3;
            LOAD_STAGE(st2, (i + 2) * 32);
        } else {
            CP_COMMIT();
        }
        uint32_t base = sb + st * 16384;
#pragma unroll
        for (int kk = 0; kk < 2; kk++) {
            int ks16 = kk * 16;
            uint32_t a[2][4];
#pragma unroll
            for (int mt = 0; mt < 2; mt++) {
                int row = wm * 32 + mt * 16 + (lane & 15);
                int ch = (ks16 >> 3) + (lane >> 4);
                uint32_t ad = base + row * 64 + ((ch ^ ((row >> 1) & 3)) << 4);
                LDSM_X4(a[mt][0], a[mt][1], a[mt][2], a[mt][3], ad);
            }
#pragma unroll
            for (int p = 0; p < 4; p++) {
                int k = ks16 + (lane & 15);
                int ch = wn * 8 + p * 2 + (lane >> 4);
                uint32_t bd = base + 8192 + k * 256 + ((ch ^ (k & 7)) << 4);
                uint32_t b0, b1, b2, b3;
                LDSM_X4T(b0, b1, b2, b3, bd);
                uint32_t f0[2] = {b0, b1}, f1[2] = {b2, b3};
#pragma unroll
                for (int mt = 0; mt < 2; mt++) {
                    mma16816(acc[mt][2*p],     a[mt], f0);
                    mma16816(acc[mt][2*p + 1], a[mt], f1);
                }
            }
        }
        st++; if (st >= 3) st = 0;
    }
#undef LOAD_STAGE

#pragma unroll
    for (int mt = 0; mt < 2; mt++) {
#pragma unroll
        for (int nt = 0; nt < 8; nt++) {
            int c = bn + wn * 64 + nt * 8 + tg * 2;
            float bx = bias[c], by = bias[c + 1];
#pragma unroll
            for (int hh = 0; hh < 2; hh++) {
                int r = bm + wm * 32 + mt * 16 + g + hh * 8;
                float v0 = acc[mt][nt][hh*2+0] + bx;
                float v1 = acc[mt][nt][hh*2+1] + by;
                if (OUTF32 && resid) {
                    float2 rv = *(const float2*)(resid + (size_t)r * N + c);
                    v0 += rv.x; v1 += rv.y;
                }
                if (RELU) { v0 = fmaxf(v0, 0.f); v1 = fmaxf(v1, 0.f); }
                if (OUTF32)
                    *(float2*)(C + (size_t)r * N + c) = make_float2(v0, v1);
                if (OUTHALF)
                    *(__half2*)(Ch + (size_t)r * N + c) = __floats2half2_rn(v0, v1);
            }
        }
    }
}

// ============================================================
// Scores: P[bh,q,k] = (Q.K)/8 masked. smem-staged coalesced epilogue
// (single clean masked write).
// ============================================================
#define SPITCH 72
#define STPITCH 132

__global__ __launch_bounds__(256) void scores_mma(
    const __half* __restrict__ Qh, const __half* __restrict__ Kh,
    const unsigned char* __restrict__ mask, float* __restrict__ P)
{
    __shared__ union {
        struct { __half Qs[128*SPITCH]; __half Ks[128*SPITCH]; } qk;
        float stage[64*STPITCH];
    } su;

    int bh = blockIdx.z, b = bh / NH, h = bh % NH;
    int bq = blockIdx.y * 128, bk = blockIdx.x * 128;
    const __half* Qb = Qh + (size_t)(b * SEQ) * DM + h * DK;
    const __half* Kb = Kh + (size_t)(b * SEQ) * DM + h * DK;

    int tid = threadIdx.x, lane = tid & 31, warp = tid >> 5;
    int wm = warp >> 1, wn = warp & 1;
    int g = lane >> 2, tg = lane & 3;
    int m_l = tid & 127, part = tid >> 7;

    {
        const uint4* qp = (const uint4*)(Qb + (size_t)(bq + m_l) * DM + part * 32);
        const uint4* kp = (const uint4*)(Kb + (size_t)(bk + m_l) * DM + part * 32);
        uint4* qd = (uint4*)(su.qk.Qs + m_l * SPITCH + part * 32);
        uint4* kd = (uint4*)(su.qk.Ks + m_l * SPITCH + part * 32);
#pragma unroll
        for (int j = 0; j < 4; j++) { qd[j] = qp[j]; kd[j] = kp[j]; }
    }
    __syncthreads();

    float acc[2][8][4];
#pragma unroll
    for (int mt = 0; mt < 2; mt++)
#pragma unroll
        for (int nt = 0; nt < 8; nt++)
#pragma unroll
            for (int q = 0; q < 4; q++) acc[mt][nt][q] = 0.f;

#pragma unroll
    for (int ks16 = 0; ks16 < 64; ks16 += 16) {
        uint32_t a[2][4];
#pragma unroll
        for (int mt = 0; mt < 2; mt++) {
            int r = wm * 32 + mt * 16 + g;
            a[mt][0] = *(const uint32_t*)(su.qk.Qs + r*SPITCH + ks16 + tg*2);
            a[mt][1] = *(const uint32_t*)(su.qk.Qs + (r+8)*SPITCH + ks16 + tg*2);
            a[mt][2] = *(const uint32_t*)(su.qk.Qs + r*SPITCH + ks16 + 8 + tg*2);
            a[mt][3] = *(const uint32_t*)(su.qk.Qs + (r+8)*SPITCH + ks16 + 8 + tg*2);
        }
#pragma unroll
        for (int nt = 0; nt < 8; nt++) {
            int cn = wn * 64 + nt * 8 + g;
            uint32_t bfr[2];
            bfr[0] = *(const uint32_t*)(su.qk.Ks + cn*SPITCH + ks16 + tg*2);
            bfr[1] = *(const uint32_t*)(su.qk.Ks + cn*SPITCH + ks16 + 8 + tg*2);
#pragma unroll
            for (int mt = 0; mt < 2; mt++) mma16816(acc[mt][nt], a[mt], bfr);
        }
    }

    const unsigned char* mrow = mask + (size_t)b * SEQ * SEQ;
    float* Pb = P + (size_t)bh * SEQ * SEQ;

    int lr_o = tid & 63, cs = (tid >> 6) * 32;
#pragma unroll
    for (int round = 0; round < 2; round++) {
        __syncthreads();
        if ((wm >> 1) == round) {
#pragma unroll
            for (int mt = 0; mt < 2; mt++)
#pragma unroll
                for (int nt = 0; nt < 8; nt++)
#pragma unroll
                    for (int hh = 0; hh < 2; hh++) {
                        int lr = (wm & 1) * 32 + mt * 16 + g + hh * 8;
                        int c = wn * 64 + nt * 8 + tg * 2;
                        *(float2*)(su.stage + lr * STPITCH + c) =
                            make_float2(acc[mt][nt][hh*2], acc[mt][nt][hh*2+1]);
                    }
        }
        __syncthreads();
        {
            int q = bq + round * 64 + lr_o;
            const unsigned char* mp = mrow + (size_t)q * SEQ + bk + cs;
            uint4 mw0 = *(const uint4*)mp;
            uint4 mw1 = *(const uint4*)(mp + 16);
            uint32_t mws[8] = {mw0.x, mw0.y, mw0.z, mw0.w, mw1.x, mw1.y, mw1.z, mw1.w};
            float* op = Pb + (size_t)q * SEQ + bk + cs;
            const float* sp = su.stage + lr_o * STPITCH + cs;
#pragma unroll
            for (int j4 = 0; j4 < 8; j4++) {
                float4 v = *(const float4*)(sp + j4 * 4);
                v.x *= 0.125f; v.y *= 0.125f; v.z *= 0.125f; v.w *= 0.125f;
                uint32_t w = mws[j4];
                if ((w >>  0) & 0xFF) v.x = -1e9f;
                if ((w >>  8) & 0xFF) v.y = -1e9f;
                if ((w >> 16) & 0xFF) v.z = -1e9f;
                if ((w >> 24) & 0xFF) v.w = -1e9f;
                *(float4*)(op + j4 * 4) = v;
            }
        }
    }
}

// ============================================================
// Row softmax over SEQ=2048, in place (f32) + fp16 copy for PV.
// float4 vectorized: thread t owns cols [i*512 + t*4, +4).
// ============================================================
__global__ __launch_bounds__(128) void softmax_kernel(
    float* __restrict__ P, __half* __restrict__ Ph)
{
    size_t row = blockIdx.x;
    float* p = P + row * (size_t)SEQ;
    __half* ph = Ph + row * (size_t)SEQ;
    int tid = threadIdx.x;
    int lane = tid & 31, warp = tid >> 5;
    __shared__ float sred[4];

    float4 v[4];
    float m = -1e30f;
#pragma unroll
    for (int i = 0; i < 4; i++) {
        v[i] = *(const float4*)(p + i * 512 + tid * 4);
        m = fmaxf(m, fmaxf(fmaxf(v[i].x, v[i].y), fmaxf(v[i].z, v[i].w)));
    }
#pragma unroll
    for (int o = 16; o > 0; o >>= 1) m = fmaxf(m, __shfl_xor_sync(0xffffffffu, m, o));
    if (lane == 0) sred[warp] = m;
    __syncthreads();
    m = fmaxf(fmaxf(sred[0], sred[1]), fmaxf(sred[2], sred[3]));
    __syncthreads();

    float s = 0.f;
#pragma unroll
    for (int i = 0; i < 4; i++) {
        v[i].x = __expf(v[i].x - m); v[i].y = __expf(v[i].y - m);
        v[i].z = __expf(v[i].z - m); v[i].w = __expf(v[i].w - m);
        s += v[i].x + v[i].y + v[i].z + v[i].w;
    }
#pragma unroll
    for (int o = 16; o > 0; o >>= 1) s += __shfl_xor_sync(0xffffffffu, s, o);
    if (lane == 0) sred[warp] = s;
    __syncthreads();
    s = sred[0] + sred[1] + sred[2] + sred[3];
    float inv = 1.f / s;
#pragma unroll
    for (int i = 0; i < 4; i++) {
        v[i].x *= inv; v[i].y *= inv; v[i].z *= inv; v[i].w *= inv;
        *(float4*)(p + i * 512 + tid * 4) = v[i];
        __half2 h0 = __floats2half2_rn(v[i].x, v[i].y);
        __half2 h1 = __floats2half2_rn(v[i].z, v[i].w);
        *(uint2*)(ph + i * 512 + tid * 4) =
            make_uint2(*(uint32_t*)&h0, *(uint32_t*)&h1);
    }
}

// ============================================================
// PV: ctx_h = Pn(fp16)[SEQ,SEQ] @ V(fp16). 128x64 block, BK=32,
// 3-stage cp.async, ldmatrix. Warp tile 32x32 (wm 0..3, wn 0..1).
// stage: A 8KB (128x32h, pitch 64B, swz c^((r>>1)&3)) + B 4KB (32x64h,
// pitch 128B, swz c^(k&7)). 3 stages = 36864 B static.
// ============================================================
__global__ __launch_bounds__(256, 3) void pv_h(
    const __half* __restrict__ Ph, const __half* __restrict__ Vh,
    __half* __restrict__ ctxh)
{
    __shared__ char psm[3 * 12288];
    uint32_t sb = smem_u32(psm);

    int bh = blockIdx.y, b = bh / NH, h = bh % NH;
    int bm = blockIdx.x * 128;
    const __half* Pb = Ph + (size_t)bh * SEQ * SEQ;
    const __half* Vb = Vh + (size_t)(b * SEQ) * DM + h * DK;

    int tid = threadIdx.x, lane = tid & 31, warp = tid >> 5;
    int wm = warp >> 1, wn = warp & 1;
    int g = lane >> 2, tg = lane & 3;

    float acc[2][4][4];
#pragma unroll
    for (int mt = 0; mt < 2; mt++)
#pragma unroll
        for (int nt = 0; nt < 4; nt++)
#pragma unroll
            for (int q = 0; q < 4; q++) acc[mt][nt][q] = 0.f;

    int ar0 = tid >> 2, ac0 = tid & 3;     // A: 2 rows each (r, r+64)
    int bk0 = tid >> 3, bc0 = tid & 7;     // B: 1 chunk each (32 rows x 8 chunks)

#define PV_LOAD(stg, k0) { \
    uint32_t base = sb + (stg) * 12288; \
    _Pragma("unroll") \
    for (int j = 0; j < 2; j++) { \
        int r = ar0 + j * 64, c = ac0; \
        uint32_t sa = base + r * 64 + ((c ^ ((r >> 1) & 3)) << 4); \
        CP_ASYNC16(sa, Pb + (size_t)(bm + r) * SEQ + (k0) + c * 8); \
    } \
    { \
        uint32_t sa = base + 8192 + bk0 * 128 + ((bc0 ^ (bk0 & 7)) << 4); \
        CP_ASYNC16(sa, Vb + (size_t)((k0) + bk0) * DM + bc0 * 8); \
    } \
    CP_COMMIT(); }

    PV_LOAD(0, 0);
    PV_LOAD(1, 32);

    const int NC = SEQ / 32;
    int st = 0;
    for (int i = 0; i < NC; i++) {
        CP_WAIT_GROUP(1);
        __syncthreads();
        if (i + 2 < NC) {
            int st2 = st + 2; if (st2 >= 3) st2 -= 3;
            PV_LOAD(st2, (i + 2) * 32);
        } else {
            CP_COMMIT();
        }
        uint32_t base = sb + st * 12288;
#pragma unroll
        for (int kk = 0; kk < 2; kk++) {
            int ks16 = kk * 16;
            uint32_t a[2][4];
#pragma unroll
            for (int mt = 0; mt < 2; mt++) {
                int row = wm * 32 + mt * 16 + (lane & 15);
                int ch = (ks16 >> 3) + (lane >> 4);
                uint32_t ad = base + row * 64 + ((ch ^ ((row >> 1) & 3)) << 4);
                LDSM_X4(a[mt][0], a[mt][1], a[mt][2], a[mt][3], ad);
            }
#pragma unroll
            for (int p = 0; p < 2; p++) {
                int k = ks16 + (lane & 15);
                int ch = wn * 4 + p * 2 + (lane >> 4);
                uint32_t bd = base + 8192 + k * 128 + ((ch ^ (k & 7)) << 4);
                uint32_t b0, b1, b2, b3;
                LDSM_X4T(b0, b1, b2, b3, bd);
                uint32_t f0[2] = {b0, b1}, f1[2] = {b2, b3};
#pragma unroll
                for (int mt = 0; mt < 2; mt++) {
                    mma16816(acc[mt][2*p],     a[mt], f0);
                    mma16816(acc[mt][2*p + 1], a[mt], f1);
                }
            }
        }
        st++; if (st >= 3) st = 0;
    }
#undef PV_LOAD

#pragma unroll
    for (int mt = 0; mt < 2; mt++)
#pragma unroll
        for (int nt = 0; nt < 4; nt++) {
            int dn = wn * 32 + nt * 8 + tg * 2;
#pragma unroll
            for (int hh = 0; hh < 2; hh++) {
                int r = bm + wm * 32 + mt * 16 + g + hh * 8;
                *(__half2*)(ctxh + (size_t)(b * SEQ + r) * DM + h * DK + dn) =
                    __floats2half2_rn(acc[mt][nt][hh*2], acc[mt][nt][hh*2+1]);
            }
        }
}

// ============================================================
// LayerNorm over last dim (768); optional fp16 copy of output.
// ============================================================
template<int OUTH>
__global__ __launch_bounds__(256) void layernorm_kernel(
    const float* __restrict__ X, const float* __restrict__ gam,
    const float* __restrict__ bet, float* __restrict__ Y, __half* __restrict__ Yh)
{
    int row = blockIdx.x;
    const float* x = X + (size_t)row * DM;
    float* y = Y + (size_t)row * DM;
    int tid = threadIdx.x;
    int lane = tid & 31, warp = tid >> 5;
    __shared__ float sw[8];

    float v0 = x[tid], v1 = x[tid + 256], v2 = x[tid + 512];
    float s = v0 + v1 + v2;
#pragma unroll
    for (int o = 16; o > 0; o >>= 1) s += __shfl_xor_sync(0xffffffffu, s, o);
    if (lane == 0) sw[warp] = s;
    __syncthreads();
    s = 0.f;
#pragma unroll
    for (int w = 0; w < 8; w++) s += sw[w];
    float mean = s * (1.f / 768.f);
    __syncthreads();

    float d0 = v0 - mean, d1 = v1 - mean, d2 = v2 - mean;
    float sq = d0 * d0 + d1 * d1 + d2 * d2;
#pragma unroll
    for (int o = 16; o > 0; o >>= 1) sq += __shfl_xor_sync(0xffffffffu, sq, o);
    if (lane == 0) sw[warp] = sq;
    __syncthreads();
    sq = 0.f;
#pragma unroll
    for (int w = 0; w < 8; w++) sq += sw[w];
    float var = sq * (1.f / 768.f);
    float rstd = rsqrtf(var + 1e-5f);

    float o0 = d0 * rstd * gam[tid]       + bet[tid];
    float o1 = d1 * rstd * gam[tid + 256] + bet[tid + 256];
    float o2 = d2 * rstd * gam[tid + 512] + bet[tid + 512];
    y[tid] = o0; y[tid + 256] = o1; y[tid + 512] = o2;
    if (OUTH) {
        __half* yh = Yh + (size_t)row * DM;
        yh[tid] = __float2half(o0);
        yh[tid + 256] = __float2half(o1);
        yh[tid + 512] = __float2half(o2);
    }
}

// ============================================================
#define HG_SMEM 49152

extern "C" void kernel_launch(void* const* d_in, const int* in_sizes, int n_in,
                              void* d_out, int out_size)
{
    const float* x    = (const float*)d_in[0];
    const unsigned char* mask = (const unsigned char*)d_in[1];
    const float* Wq = (const float*)d_in[2];
    const float* bq = (const float*)d_in[3];
    const float* Wk = (const float*)d_in[4];
    const float* bk = (const float*)d_in[5];
    const float* Wv = (const float*)d_in[6];
    const float* bv = (const float*)d_in[7];
    const float* Wo = (const float*)d_in[8];
    const float* bo = (const float*)d_in[9];
    const float* ln1g = (const float*)d_in[10];
    const float* ln1b = (const float*)d_in[11];
    const float* W1 = (const float*)d_in[12];
    const float* b1 = (const float*)d_in[13];
    const float* W2 = (const float*)d_in[14];
    const float* b2 = (const float*)d_in[15];
    const float* ln2g = (const float*)d_in[16];
    const float* ln2b = (const float*)d_in[17];
    float* out = (float*)d_out;

    __half *xh, *Wqh, *Wkh, *Wvh, *Woh, *W1h, *W2h;
    __half *Qh, *Kh, *Vh, *Phh, *ctxh, *aoh, *hh;
    float *Pd, *t0, *ao, *f;
    cudaGetSymbolAddress((void**)&xh,   g_xh);
    cudaGetSymbolAddress((void**)&Wqh,  g_Wqh);
    cudaGetSymbolAddress((void**)&Wkh,  g_Wkh);
    cudaGetSymbolAddress((void**)&Wvh,  g_Wvh);
    cudaGetSymbolAddress((void**)&Woh,  g_Woh);
    cudaGetSymbolAddress((void**)&W1h,  g_W1h);
    cudaGetSymbolAddress((void**)&W2h,  g_W2h);
    cudaGetSymbolAddress((void**)&Qh,   g_Qh);
    cudaGetSymbolAddress((void**)&Kh,   g_Kh);
    cudaGetSymbolAddress((void**)&Vh,   g_Vh);
    cudaGetSymbolAddress((void**)&Phh,  g_Ph);
    cudaGetSymbolAddress((void**)&ctxh, g_ctxh);
    cudaGetSymbolAddress((void**)&aoh,  g_aoh);
    cudaGetSymbolAddress((void**)&hh,   g_hh);
    cudaGetSymbolAddress((void**)&Pd,   g_P);
    cudaGetSymbolAddress((void**)&t0,   g_t0);
    cudaGetSymbolAddress((void**)&ao,   g_ao);
    cudaGetSymbolAddress((void**)&f,    g_f);

    cudaFuncSetAttribute(hgemm<0,0,1>, cudaFuncAttributeMaxDynamicSharedMemorySize, HG_SMEM);
    cudaFuncSetAttribute(hgemm<0,1,0>, cudaFuncAttributeMaxDynamicSharedMemorySize, HG_SMEM);
    cudaFuncSetAttribute(hgemm<1,0,1>, cudaFuncAttributeMaxDynamicSharedMemorySize, HG_SMEM);

    float* Pbuf = ((size_t)out_size >= (size_t)OUT_ELEMS + ATT_ELEMS)
                ? (out + OUT_ELEMS) : Pd;

    f2h_kernel<<<(MROWS*DM)/1024, 256>>>(x,  xh);
    f2h_kernel<<<(DM*DM)/1024,  256>>>(Wq, Wqh);
    f2h_kernel<<<(DM*DM)/1024,  256>>>(Wk, Wkh);
    f2h_kernel<<<(DM*DM)/1024,  256>>>(Wv, Wvh);
    f2h_kernel<<<(DM*DM)/1024,  256>>>(Wo, Woh);
    f2h_kernel<<<(DM*DFF)/1024, 256>>>(W1, W1h);
    f2h_kernel<<<(DFF*DM)/1024, 256>>>(W2, W2h);

    dim3 g768(DM / 128, MROWS / 128);
    hgemm<0,0,1><<<g768, 256, HG_SMEM>>>(xh, Wqh, bq, nullptr, nullptr, Qh, MROWS, DM, DM);
    hgemm<0,0,1><<<g768, 256, HG_SMEM>>>(xh, Wkh, bk, nullptr, nullptr, Kh, MROWS, DM, DM);
    hgemm<0,0,1><<<g768, 256, HG_SMEM>>>(xh, Wvh, bv, nullptr, nullptr, Vh, MROWS, DM, DM);

    dim3 gs(SEQ / 128, SEQ / 128, BHN);
    scores_mma<<<gs, 256>>>(Qh, Kh, mask, Pbuf);
    softmax_kernel<<<BHN * SEQ, 128>>>(Pbuf, Phh);

    dim3 gpv(SEQ / 128, BHN);
    pv_h<<<gpv, 256>>>(Phh, Vh, ctxh);

    hgemm<0,1,0><<<g768, 256, HG_SMEM>>>(ctxh, Woh, bo, x, t0, nullptr, MROWS, DM, DM);
    layernorm_kernel<1><<<MROWS, 256>>>(t0, ln1g, ln1b, ao, aoh);

    dim3 gff1(DFF / 128, MROWS / 128);
    hgemm<1,0,1><<<gff1, 256, HG_SMEM>>>(aoh, W1h, b1, nullptr, nullptr, hh, MROWS, DFF, DM);
    hgemm<0,1,0><<<g768, 256, HG_SMEM>>>(hh, W2h, b2, ao, f, nullptr, MROWS, DM, DFF);
    layernorm_kernel<0><<<MROWS, 256>>>(f, ln2g, ln2b, out, nullptr);
}